// round 9
// baseline (speedup 1.0000x reference)
#include <cuda_runtime.h>
#include <cuda_bf16.h>
#include <cstdint>

#define NT 256
#define DD 256
#define NEG_BIG (-1e30f)

// ---- smem byte offsets (from 128B-aligned base) ----
#define QHI_OFF 0          // [128][256] bf16 hi, 512B/row, swizzled
#define QLO_OFF 65536      // [128][256] bf16 lo
#define KHI_OFF 131072     // [64][256] bf16 hi (K and V view of s2 tile)
#define KLO_OFF 163840
#define RAW_OFF 196608     // [32][256] f32 staging (half tile)
#define P1_OFF  229376     // 128 f32
#define P2_OFF  229888     // 64 f32
#define SMEM_USED 230144
#define SMEM_BYTES (SMEM_USED + 128)

__device__ __forceinline__ uint32_t smem_u32(const void* p) {
    uint32_t a;
    asm("{ .reg .u64 t; cvta.to.shared.u64 t, %1; cvt.u32.u64 %0, t; }"
        : "=r"(a) : "l"(p));
    return a;
}

#define CP_ASYNC16(dst, src) \
    asm volatile("cp.async.cg.shared.global [%0], [%1], 16;" \
        :: "r"(dst), "l"(src) : "memory")
#define CP_COMMIT() asm volatile("cp.async.commit_group;" ::: "memory")
#define CP_WAIT0()  asm volatile("cp.async.wait_group 0;" ::: "memory")

__device__ __forceinline__ void ldsm_x4(uint32_t& a0, uint32_t& a1, uint32_t& a2,
                                        uint32_t& a3, uint32_t addr) {
    asm volatile("ldmatrix.sync.aligned.m8n8.x4.shared.b16 {%0,%1,%2,%3}, [%4];"
                 : "=r"(a0), "=r"(a1), "=r"(a2), "=r"(a3) : "r"(addr));
}
__device__ __forceinline__ void ldsm_x4t(uint32_t& a0, uint32_t& a1, uint32_t& a2,
                                         uint32_t& a3, uint32_t addr) {
    asm volatile("ldmatrix.sync.aligned.m8n8.x4.trans.shared.b16 {%0,%1,%2,%3}, [%4];"
                 : "=r"(a0), "=r"(a1), "=r"(a2), "=r"(a3) : "r"(addr));
}
__device__ __forceinline__ void mma16816(float* c, uint32_t a0, uint32_t a1,
                                         uint32_t a2, uint32_t a3,
                                         uint32_t b0, uint32_t b1) {
    asm volatile(
        "mma.sync.aligned.m16n8k16.row.col.f32.bf16.bf16.f32 "
        "{%0,%1,%2,%3}, {%4,%5,%6,%7}, {%8,%9}, {%0,%1,%2,%3};"
        : "+f"(c[0]), "+f"(c[1]), "+f"(c[2]), "+f"(c[3])
        : "r"(a0), "r"(a1), "r"(a2), "r"(a3), "r"(b0), "r"(b1));
}

// swizzled chunk address: 16B chunks, XOR low-3 chunk bits with row&7
__device__ __forceinline__ uint32_t swz(int row, int chunk, int rowbytes) {
    int c = (chunk & ~7) | ((chunk & 7) ^ (row & 7));
    return (uint32_t)(row * rowbytes + c * 16);
}

__device__ __forceinline__ uint32_t pk2(__nv_bfloat16 a, __nv_bfloat16 b) {
    __nv_bfloat162 t; t.x = a; t.y = b;
    return *reinterpret_cast<uint32_t*>(&t);
}

// split 2 floats into packed bf16 hi + residual lo
__device__ __forceinline__ void split2(float a, float b, uint32_t& hi, uint32_t& lo) {
    __nv_bfloat16 ha = __float2bfloat16(a), hb = __float2bfloat16(b);
    float ra = a - __bfloat162float(ha), rb = b - __bfloat162float(hb);
    hi = pk2(ha, hb);
    lo = pk2(__float2bfloat16(ra), __float2bfloat16(rb));
}

__global__ void __launch_bounds__(NT, 1)
bidaf_fa2(const float* __restrict__ s1, const float* __restrict__ s2,
          const float* __restrict__ w, const int* __restrict__ l1,
          const int* __restrict__ l2, float* __restrict__ out)
{
    extern __shared__ char sm_raw[];
    char* smc = (char*)(((uintptr_t)sm_raw + 127) & ~(uintptr_t)127);

    const int b   = blockIdx.y;
    const int m0  = blockIdx.x * 128;
    const int tid = threadIdx.x;
    const int L1v = l1[b], L2v = l2[b];
    float* outTile = out + ((size_t)b * 1024 + m0) * DD;

    if (m0 >= L1v || L2v == 0) {
        float4 z = make_float4(0.f, 0.f, 0.f, 0.f);
        for (int i = tid; i < 128 * DD / 4; i += NT) ((float4*)outTile)[i] = z;
        return;
    }

    const uint32_t smem = smem_u32(smc);
    const int lane = tid & 31;
    const int wid  = tid >> 5;

    const float* s1b = s1 + ((size_t)b * 1024 + m0) * DD;
    const float* s2b = s2 + (size_t)b * 1024 * DD;
    const float4* w1v = (const float4*)w;
    const float4* w2v = (const float4*)(w + DD);
    const float4* w3v = (const float4*)(w + 2 * DD);

    const int crow = tid >> 3, chh = tid & 7;   // convert mapping: 8 threads/row

    // ---- issue gA(tile0, rows 0-31) into RAW ----
    {
        const char* src = (const char*)(s2b + (size_t)crow * DD);
        uint32_t dst = smem + RAW_OFF + (uint32_t)crow * 1024;
        #pragma unroll
        for (int p = 0; p < 8; p++) {
            int c4 = chh + 8 * p;
            CP_ASYNC16(dst + c4 * 16, src + c4 * 16);
        }
        CP_COMMIT();
    }

    // ---------------- prologue: Q = s1*w3 -> bf16 hi/lo smem; part1 ----------------
    {
        const int row = tid >> 1, h = tid & 1;
        const float4* qr = (const float4*)(s1b + row * DD);
        float acc = 0.f;
        #pragma unroll
        for (int i = 0; i < 32; i++) {
            int c4 = 2 * i + h;
            float4 v = qr[c4];
            float4 a1 = w1v[c4];
            acc += v.x * a1.x + v.y * a1.y + v.z * a1.z + v.w * a1.w;
            float4 m3 = w3v[c4];
            float q0 = v.x * m3.x, q1 = v.y * m3.y, q2 = v.z * m3.z, q3 = v.w * m3.w;
            uint32_t hA, lA, hB, lB;
            split2(q0, q1, hA, lA); split2(q2, q3, hB, lB);
            uint32_t off = swz(row, i, 512) + h * 8;
            *(uint2*)(smc + QHI_OFF + off) = make_uint2(hA, hB);
            *(uint2*)(smc + QLO_OFF + off) = make_uint2(lA, lB);
        }
        acc += __shfl_xor_sync(0xffffffffu, acc, 1);
        if (h == 0) ((float*)(smc + P1_OFF))[row] = acc;
    }
    __syncthreads();

    const int r0l = wid * 16 + (lane >> 2);     // this thread's c-frag row (and +8)
    const float p1a = ((const float*)(smc + P1_OFF))[r0l];
    const float p1b = ((const float*)(smc + P1_OFF))[r0l + 8];
    const int lam = lane & 3;                   // col pair owner

    float O[32][4];
    #pragma unroll
    for (int j = 0; j < 32; j++)
        #pragma unroll
        for (int e = 0; e < 4; e++) O[j][e] = 0.f;
    float mrow0 = -INFINITY, mrow1 = -INFINITY, lrow0 = 0.f, lrow1 = 0.f;

    const float4* rawv = (const float4*)(smc + RAW_OFF);
    const float* p2f = (const float*)(smc + P2_OFF);

    const int arow = wid * 16 + (lane & 15);
    const int brow = (lane & 7) + ((lane >> 4) & 1) * 8;

    const int ntiles = (L2v + 63) >> 6;
    for (int t = 0; t < ntiles; t++) {
        const int n0 = t * 64;

        __syncthreads();       // prior PV done reading K
        CP_WAIT0();            // gA(t): rows n0..n0+31 staged

        // ---- convert half0 (K rows 0-31 of tile) + part2; then issue gB ----
        {
            float acc = 0.f;
            const float4* slot = rawv + crow * 64;
            #pragma unroll
            for (int p = 0; p < 8; p++) {
                int c4 = chh + 8 * p;
                float4 v = slot[c4];
                float4 a2 = w2v[c4];
                acc += v.x * a2.x + v.y * a2.y + v.z * a2.z + v.w * a2.w;
                uint32_t hA, lA, hB, lB;
                split2(v.x, v.y, hA, lA); split2(v.z, v.w, hB, lB);
                uint32_t off = swz(crow, c4 >> 1, 512) + (c4 & 1) * 8;
                *(uint2*)(smc + KHI_OFF + off) = make_uint2(hA, hB);
                *(uint2*)(smc + KLO_OFF + off) = make_uint2(lA, lB);
            }
            acc += __shfl_xor_sync(0xffffffffu, acc, 1);
            acc += __shfl_xor_sync(0xffffffffu, acc, 2);
            acc += __shfl_xor_sync(0xffffffffu, acc, 4);
            if (chh == 0) ((float*)(smc + P2_OFF))[crow] = acc;
            // issue gB: rows n0+32..n0+63 (this thread's slot just consumed)
            const char* src = (const char*)(s2b + (size_t)(n0 + 32 + crow) * DD);
            uint32_t dst = smem + RAW_OFF + (uint32_t)crow * 1024;
            #pragma unroll
            for (int p = 0; p < 8; p++) {
                int c4 = chh + 8 * p;
                CP_ASYNC16(dst + c4 * 16, src + c4 * 16);
            }
            CP_COMMIT();
        }
        __syncthreads();       // K rows 0-31 + P2[0..31] visible

        // ================= two 32-col sub-tiles: score -> softmax -> PV =========
        #pragma unroll 1
        for (int half = 0; half < 2; half++) {
            const int nbase = half * 32;

            // ---- score: n-cols nbase..nbase+31 -> c[0..3][4] ----
            float c[4][4];
            #pragma unroll
            for (int j = 0; j < 4; j++)
                #pragma unroll
                for (int e = 0; e < 4; e++) c[j][e] = 0.f;

            #pragma unroll 4
            for (int k = 0; k < 16; k++) {
                uint32_t aoff = swz(arow, 2 * k + (lane >> 4), 512);
                uint32_t ah0, ah1, ah2, ah3, al0, al1, al2, al3;
                ldsm_x4(ah0, ah1, ah2, ah3, smem + QHI_OFF + aoff);
                ldsm_x4(al0, al1, al2, al3, smem + QLO_OFF + aoff);
                #pragma unroll
                for (int nb = 0; nb < 2; nb++) {
                    uint32_t boff = swz(brow + nbase + nb * 16,
                                        2 * k + ((lane >> 3) & 1), 512);
                    uint32_t bh0, bh1, bh2, bh3, bl0, bl1, bl2, bl3;
                    ldsm_x4(bh0, bh1, bh2, bh3, smem + KHI_OFF + boff);
                    ldsm_x4(bl0, bl1, bl2, bl3, smem + KLO_OFF + boff);
                    mma16816(c[2 * nb], ah0, ah1, ah2, ah3, bh0, bh1);
                    mma16816(c[2 * nb + 1], ah0, ah1, ah2, ah3, bh2, bh3);
                    mma16816(c[2 * nb], ah0, ah1, ah2, ah3, bl0, bl1);
                    mma16816(c[2 * nb + 1], ah0, ah1, ah2, ah3, bl2, bl3);
                    mma16816(c[2 * nb], al0, al1, al2, al3, bh0, bh1);
                    mma16816(c[2 * nb + 1], al0, al1, al2, al3, bh2, bh3);
                }
            }

            // ---- warp-local online softmax over these 32 cols ----
            float mx0 = -INFINITY, mx1 = -INFINITY;
            #pragma unroll
            for (int j = 0; j < 4; j++) {
                #pragma unroll
                for (int e = 0; e < 2; e++) {
                    int col = nbase + j * 8 + 2 * lam + e;
                    bool valid = (n0 + col) < L2v;
                    float bias = p2f[col];
                    float s0 = c[j][e] + p1a + bias;
                    float s1v = c[j][e + 2] + p1b + bias;
                    s0 = valid ? s0 : NEG_BIG;
                    s1v = valid ? s1v : NEG_BIG;
                    c[j][e] = s0; c[j][e + 2] = s1v;
                    mx0 = fmaxf(mx0, s0); mx1 = fmaxf(mx1, s1v);
                }
            }
            mx0 = fmaxf(mx0, __shfl_xor_sync(0xffffffffu, mx0, 1));
            mx0 = fmaxf(mx0, __shfl_xor_sync(0xffffffffu, mx0, 2));
            mx1 = fmaxf(mx1, __shfl_xor_sync(0xffffffffu, mx1, 1));
            mx1 = fmaxf(mx1, __shfl_xor_sync(0xffffffffu, mx1, 2));

            const float mnew0 = fmaxf(mrow0, mx0), mnew1 = fmaxf(mrow1, mx1);
            const float alpha0 = __expf(mrow0 - mnew0), alpha1 = __expf(mrow1 - mnew1);
            mrow0 = mnew0; mrow1 = mnew1;

            float sum0 = 0.f, sum1 = 0.f;
            #pragma unroll
            for (int j = 0; j < 4; j++) {
                c[j][0] = __expf(c[j][0] - mnew0);
                c[j][1] = __expf(c[j][1] - mnew0);
                c[j][2] = __expf(c[j][2] - mnew1);
                c[j][3] = __expf(c[j][3] - mnew1);
                sum0 += c[j][0] + c[j][1];
                sum1 += c[j][2] + c[j][3];
            }
            sum0 += __shfl_xor_sync(0xffffffffu, sum0, 1);
            sum0 += __shfl_xor_sync(0xffffffffu, sum0, 2);
            sum1 += __shfl_xor_sync(0xffffffffu, sum1, 1);
            sum1 += __shfl_xor_sync(0xffffffffu, sum1, 2);
            lrow0 = lrow0 * alpha0 + sum0;
            lrow1 = lrow1 * alpha1 + sum1;

            // ---- pack P c-frags into PV a-frags (in registers) ----
            uint32_t pah[8], pal[8];
            #pragma unroll
            for (int kk = 0; kk < 2; kk++) {
                const int J = 2 * kk;
                split2(c[J][0],     c[J][1],     pah[4 * kk + 0], pal[4 * kk + 0]);
                split2(c[J][2],     c[J][3],     pah[4 * kk + 1], pal[4 * kk + 1]);
                split2(c[J + 1][0], c[J + 1][1], pah[4 * kk + 2], pal[4 * kk + 2]);
                split2(c[J + 1][2], c[J + 1][3], pah[4 * kk + 3], pal[4 * kk + 3]);
            }

            // ---- rescale O ----
            #pragma unroll
            for (int j = 0; j < 32; j++) {
                O[j][0] *= alpha0; O[j][1] *= alpha0;
                O[j][2] *= alpha1; O[j][3] *= alpha1;
            }

            // ---- PV: O += P(:, nbase..nbase+31) * V(nbase..nbase+31, :) ----
            #pragma unroll
            for (int kk = 0; kk < 2; kk++) {
                const int vrow = nbase + kk * 16 + (lane & 15);
                const uint32_t a0 = pah[4 * kk], a1 = pah[4 * kk + 1],
                               a2 = pah[4 * kk + 2], a3 = pah[4 * kk + 3];
                const uint32_t b0 = pal[4 * kk], b1 = pal[4 * kk + 1],
                               b2 = pal[4 * kk + 2], b3 = pal[4 * kk + 3];
                #pragma unroll
                for (int dblk = 0; dblk < 16; dblk++) {
                    uint32_t boff = swz(vrow, 2 * dblk + (lane >> 4), 512);
                    uint32_t vh0, vh1, vh2, vh3, vl0, vl1, vl2, vl3;
                    ldsm_x4t(vh0, vh1, vh2, vh3, smem + KHI_OFF + boff);
                    ldsm_x4t(vl0, vl1, vl2, vl3, smem + KLO_OFF + boff);
                    mma16816(O[2 * dblk],     a0, a1, a2, a3, vh0, vh1);
                    mma16816(O[2 * dblk + 1], a0, a1, a2, a3, vh2, vh3);
                    mma16816(O[2 * dblk],     a0, a1, a2, a3, vl0, vl1);
                    mma16816(O[2 * dblk + 1], a0, a1, a2, a3, vl2, vl3);
                    mma16816(O[2 * dblk],     b0, b1, b2, b3, vh0, vh1);
                    mma16816(O[2 * dblk + 1], b0, b1, b2, b3, vh2, vh3);
                }
            }

            // ---- between halves: land gB, convert half1, issue gA(t+1) ----
            if (half == 0) {
                CP_WAIT0();
                {
                    float acc = 0.f;
                    const int krow = 32 + crow;
                    const float4* slot = rawv + crow * 64;
                    #pragma unroll
                    for (int p = 0; p < 8; p++) {
                        int c4 = chh + 8 * p;
                        float4 v = slot[c4];
                        float4 a2 = w2v[c4];
                        acc += v.x * a2.x + v.y * a2.y + v.z * a2.z + v.w * a2.w;
                        uint32_t hA, lA, hB, lB;
                        split2(v.x, v.y, hA, lA); split2(v.z, v.w, hB, lB);
                        uint32_t off = swz(krow, c4 >> 1, 512) + (c4 & 1) * 8;
                        *(uint2*)(smc + KHI_OFF + off) = make_uint2(hA, hB);
                        *(uint2*)(smc + KLO_OFF + off) = make_uint2(lA, lB);
                    }
                    acc += __shfl_xor_sync(0xffffffffu, acc, 1);
                    acc += __shfl_xor_sync(0xffffffffu, acc, 2);
                    acc += __shfl_xor_sync(0xffffffffu, acc, 4);
                    if (chh == 0) ((float*)(smc + P2_OFF))[krow] = acc;
                    if (t + 1 < ntiles) {
                        const char* src = (const char*)(s2b + (size_t)(n0 + 64 + crow) * DD);
                        uint32_t dst = smem + RAW_OFF + (uint32_t)crow * 1024;
                        #pragma unroll
                        for (int p = 0; p < 8; p++) {
                            int c4 = chh + 8 * p;
                            CP_ASYNC16(dst + c4 * 16, src + c4 * 16);
                        }
                        CP_COMMIT();
                    }
                }
                __syncthreads();   // K rows 32-63 + P2[32..63] visible
            }
        }
    }

    // ---------------- epilogue ----------------
    const int gr0 = m0 + r0l, gr1 = gr0 + 8;
    const float inv0 = (gr0 < L1v) ? (1.f / lrow0) : 0.f;
    const float inv1 = (gr1 < L1v) ? (1.f / lrow1) : 0.f;
    float* orow0 = outTile + r0l * DD + 2 * lam;
    float* orow1 = orow0 + 8 * DD;
    #pragma unroll
    for (int j = 0; j < 32; j++) {
        float2 v0; v0.x = O[j][0] * inv0; v0.y = O[j][1] * inv0;
        float2 v1; v1.x = O[j][2] * inv1; v1.y = O[j][3] * inv1;
        *(float2*)(orow0 + j * 8) = v0;
        *(float2*)(orow1 + j * 8) = v1;
    }
}

extern "C" void kernel_launch(void* const* d_in, const int* in_sizes, int n_in,
                              void* d_out, int out_size)
{
    const float* s1 = (const float*)d_in[0];
    const float* s2 = (const float*)d_in[1];
    const float* w  = (const float*)d_in[2];
    const int*   l1 = (const int*)d_in[3];
    const int*   l2 = (const int*)d_in[4];
    float* out = (float*)d_out;

    const int B  = in_sizes[3];
    const int D  = in_sizes[2] / 3;
    const int t1 = in_sizes[0] / (B * D);

    cudaFuncSetAttribute(bidaf_fa2, cudaFuncAttributeMaxDynamicSharedMemorySize,
                         SMEM_BYTES);
    dim3 grid(t1 / 128, B);
    bidaf_fa2<<<grid, NT, SMEM_BYTES>>>(s1, s2, w, l1, l2, out);
}

// round 10
// speedup vs baseline: 1.1230x; 1.1230x over previous
#include <cuda_runtime.h>
#include <cuda_bf16.h>
#include <cstdint>

#define NT 256
#define DD 256
#define NEG_BIG (-1e30f)

// ---- static scratch: converted s2 (swizzle baked into 512B rows) + part2 ----
#define MAXROWS (32 * 1024)
__device__ __align__(128) char  g_s2hi[(size_t)MAXROWS * 512];
__device__ __align__(128) char  g_s2lo[(size_t)MAXROWS * 512];
__device__ __align__(128) float g_part2[MAXROWS];

// ---- smem byte offsets (from 128B-aligned base) ----
#define QHI_OFF 0           // [128][256] bf16 hi, 512B/row, swizzled
#define QLO_OFF 65536       // [128][256] bf16 lo
#define KBUF_OFF 131072     // 2 x { KHI 16KB, KLO 16KB }
#define KBUF_STRIDE 32768
#define P2_OFF  196608      // 2 x 128B bias slices
#define P1_OFF  196864      // 128 f32
#define SMEM_USED 197376
#define SMEM_BYTES (SMEM_USED + 128)

__device__ __forceinline__ uint32_t smem_u32(const void* p) {
    uint32_t a;
    asm("{ .reg .u64 t; cvta.to.shared.u64 t, %1; cvt.u32.u64 %0, t; }"
        : "=r"(a) : "l"(p));
    return a;
}

#define CP_ASYNC16(dst, src) \
    asm volatile("cp.async.cg.shared.global [%0], [%1], 16;" \
        :: "r"(dst), "l"(src) : "memory")
#define CP_COMMIT() asm volatile("cp.async.commit_group;" ::: "memory")
#define CP_WAIT0()  asm volatile("cp.async.wait_group 0;" ::: "memory")

__device__ __forceinline__ void ldsm_x4(uint32_t& a0, uint32_t& a1, uint32_t& a2,
                                        uint32_t& a3, uint32_t addr) {
    asm volatile("ldmatrix.sync.aligned.m8n8.x4.shared.b16 {%0,%1,%2,%3}, [%4];"
                 : "=r"(a0), "=r"(a1), "=r"(a2), "=r"(a3) : "r"(addr));
}
__device__ __forceinline__ void ldsm_x4t(uint32_t& a0, uint32_t& a1, uint32_t& a2,
                                         uint32_t& a3, uint32_t addr) {
    asm volatile("ldmatrix.sync.aligned.m8n8.x4.trans.shared.b16 {%0,%1,%2,%3}, [%4];"
                 : "=r"(a0), "=r"(a1), "=r"(a2), "=r"(a3) : "r"(addr));
}
__device__ __forceinline__ void mma16816(float* c, uint32_t a0, uint32_t a1,
                                         uint32_t a2, uint32_t a3,
                                         uint32_t b0, uint32_t b1) {
    asm volatile(
        "mma.sync.aligned.m16n8k16.row.col.f32.bf16.bf16.f32 "
        "{%0,%1,%2,%3}, {%4,%5,%6,%7}, {%8,%9}, {%0,%1,%2,%3};"
        : "+f"(c[0]), "+f"(c[1]), "+f"(c[2]), "+f"(c[3])
        : "r"(a0), "r"(a1), "r"(a2), "r"(a3), "r"(b0), "r"(b1));
}

// swizzled chunk address: 16B chunks, XOR low-3 chunk bits with row&7
__device__ __forceinline__ uint32_t swz(int row, int chunk, int rowbytes) {
    int c = (chunk & ~7) | ((chunk & 7) ^ (row & 7));
    return (uint32_t)(row * rowbytes + c * 16);
}

__device__ __forceinline__ uint32_t pk2(__nv_bfloat16 a, __nv_bfloat16 b) {
    __nv_bfloat162 t; t.x = a; t.y = b;
    return *reinterpret_cast<uint32_t*>(&t);
}

__device__ __forceinline__ void split2(float a, float b, uint32_t& hi, uint32_t& lo) {
    __nv_bfloat16 ha = __float2bfloat16(a), hb = __float2bfloat16(b);
    float ra = a - __bfloat162float(ha), rb = b - __bfloat162float(hb);
    hi = pk2(ha, hb);
    lo = pk2(__float2bfloat16(ra), __float2bfloat16(rb));
}

// =============== prepass: s2 -> bf16 hi/lo (swizzled rows) + part2 ===============
__global__ void __launch_bounds__(256, 2)
prep_s2(const float* __restrict__ s2, const float* __restrict__ w, int total_rows)
{
    const int row = blockIdx.x * 32 + (threadIdx.x >> 3);
    const int h   = threadIdx.x & 7;
    if (row >= total_rows) return;

    const float4* sr  = (const float4*)(s2 + (size_t)row * DD);
    const float4* w2v = (const float4*)(w + DD);
    char* hrow = g_s2hi + (size_t)row * 512;
    char* lrow = g_s2lo + (size_t)row * 512;

    float acc = 0.f;
    #pragma unroll
    for (int p = 0; p < 8; p++) {
        int c4 = h + 8 * p;                 // float4 index 0..63
        float4 v = sr[c4];
        float4 a2 = w2v[c4];
        acc += v.x * a2.x + v.y * a2.y + v.z * a2.z + v.w * a2.w;
        uint32_t hA, lA, hB, lB;
        split2(v.x, v.y, hA, lA); split2(v.z, v.w, hB, lB);
        int chunk = c4 >> 1;
        uint32_t off = (uint32_t)(((chunk & ~7) | ((chunk & 7) ^ (row & 7))) * 16
                                  + (c4 & 1) * 8);
        *(uint2*)(hrow + off) = make_uint2(hA, hB);
        *(uint2*)(lrow + off) = make_uint2(lA, lB);
    }
    acc += __shfl_xor_sync(0xffffffffu, acc, 1);
    acc += __shfl_xor_sync(0xffffffffu, acc, 2);
    acc += __shfl_xor_sync(0xffffffffu, acc, 4);
    if (h == 0) g_part2[row] = acc;
}

// ============================== main kernel ==============================
__global__ void __launch_bounds__(NT, 1)
bidaf_fa2(const float* __restrict__ s1, const float* __restrict__ s2,
          const float* __restrict__ w, const int* __restrict__ l1,
          const int* __restrict__ l2, float* __restrict__ out)
{
    extern __shared__ char sm_raw[];
    char* smc = (char*)(((uintptr_t)sm_raw + 127) & ~(uintptr_t)127);

    const int b   = blockIdx.y;
    const int m0  = blockIdx.x * 128;
    const int tid = threadIdx.x;
    const int L1v = l1[b], L2v = l2[b];
    float* outTile = out + ((size_t)b * 1024 + m0) * DD;

    if (m0 >= L1v || L2v == 0) {
        float4 z = make_float4(0.f, 0.f, 0.f, 0.f);
        for (int i = tid; i < 128 * DD / 4; i += NT) ((float4*)outTile)[i] = z;
        return;
    }

    const uint32_t smem = smem_u32(smc);
    const int lane = tid & 31;
    const int wid  = tid >> 5;

    const float* s1b = s1 + ((size_t)b * 1024 + m0) * DD;
    const float4* w1v = (const float4*)w;
    const float4* w3v = (const float4*)(w + 2 * DD);

    const int bbase = b * 1024;          // row base into g_s2hi/lo/part2
    const int krr = tid >> 3, khh = tid & 7;   // K copy mapping: 8 thr/row, 32 rows

    // issue chunk 0 into buffer 0
    {
        const char* srcH = g_s2hi + (size_t)(bbase + krr) * 512;
        const char* srcL = g_s2lo + (size_t)(bbase + krr) * 512;
        uint32_t dstH = smem + KBUF_OFF + (uint32_t)krr * 512;
        uint32_t dstL = dstH + 16384;
        #pragma unroll
        for (int p = 0; p < 4; p++) {
            int ch = khh + 8 * p;
            CP_ASYNC16(dstH + ch * 16, srcH + ch * 16);
            CP_ASYNC16(dstL + ch * 16, srcL + ch * 16);
        }
        if (tid < 8)
            CP_ASYNC16(smem + P2_OFF + tid * 16,
                       (const char*)(g_part2 + bbase) + tid * 16);
        CP_COMMIT();
    }

    // ---------------- prologue: Q = s1*w3 -> bf16 hi/lo smem; part1 ----------------
    {
        const int row = tid >> 1, h = tid & 1;
        const float4* qr = (const float4*)(s1b + row * DD);
        float acc = 0.f;
        #pragma unroll
        for (int i = 0; i < 32; i++) {
            int c4 = 2 * i + h;
            float4 v = qr[c4];
            float4 a1 = w1v[c4];
            acc += v.x * a1.x + v.y * a1.y + v.z * a1.z + v.w * a1.w;
            float4 m3 = w3v[c4];
            float q0 = v.x * m3.x, q1 = v.y * m3.y, q2 = v.z * m3.z, q3 = v.w * m3.w;
            uint32_t hA, lA, hB, lB;
            split2(q0, q1, hA, lA); split2(q2, q3, hB, lB);
            uint32_t off = swz(row, i, 512) + h * 8;
            *(uint2*)(smc + QHI_OFF + off) = make_uint2(hA, hB);
            *(uint2*)(smc + QLO_OFF + off) = make_uint2(lA, lB);
        }
        acc += __shfl_xor_sync(0xffffffffu, acc, 1);
        if (h == 0) ((float*)(smc + P1_OFF))[row] = acc;
    }
    __syncthreads();   // Q + P1 visible

    const int r0l = wid * 16 + (lane >> 2);
    const float p1a = ((const float*)(smc + P1_OFF))[r0l];
    const float p1b = ((const float*)(smc + P1_OFF))[r0l + 8];
    const int lam = lane & 3;

    float O[32][4];
    #pragma unroll
    for (int j = 0; j < 32; j++)
        #pragma unroll
        for (int e = 0; e < 4; e++) O[j][e] = 0.f;
    float mrow0 = -INFINITY, mrow1 = -INFINITY, lrow0 = 0.f, lrow1 = 0.f;

    const int arow = wid * 16 + (lane & 15);
    const int brow = (lane & 7) + ((lane >> 4) & 1) * 8;

    const int nchunks = (L2v + 31) >> 5;
    for (int i = 0; i < nchunks; i++) {
        const int buf = i & 1;
        const uint32_t kh = smem + KBUF_OFF + (uint32_t)buf * KBUF_STRIDE;
        const uint32_t kl = kh + 16384;
        const float* p2f = (const float*)(smc + P2_OFF + buf * 128);
        const int c0 = i * 32;

        CP_WAIT0();          // chunk i landed
        __syncthreads();     // all warps done with buf^1's previous chunk

        // issue chunk i+1 into the other buffer
        if (i + 1 < nchunks) {
            const int cn = c0 + 32;
            const char* srcH = g_s2hi + (size_t)(bbase + cn + krr) * 512;
            const char* srcL = g_s2lo + (size_t)(bbase + cn + krr) * 512;
            uint32_t dstH = smem + KBUF_OFF + (uint32_t)(buf ^ 1) * KBUF_STRIDE
                            + (uint32_t)krr * 512;
            uint32_t dstL = dstH + 16384;
            #pragma unroll
            for (int p = 0; p < 4; p++) {
                int ch = khh + 8 * p;
                CP_ASYNC16(dstH + ch * 16, srcH + ch * 16);
                CP_ASYNC16(dstL + ch * 16, srcL + ch * 16);
            }
            if (tid < 8)
                CP_ASYNC16(smem + P2_OFF + (buf ^ 1) * 128 + tid * 16,
                           (const char*)(g_part2 + bbase + cn) + tid * 16);
            CP_COMMIT();
        }

        // ---- score: 16 rows x 32 cols, 3-term bf16 split ----
        float c[4][4];
        #pragma unroll
        for (int j = 0; j < 4; j++)
            #pragma unroll
            for (int e = 0; e < 4; e++) c[j][e] = 0.f;

        #pragma unroll 4
        for (int k = 0; k < 16; k++) {
            uint32_t aoff = swz(arow, 2 * k + (lane >> 4), 512);
            uint32_t ah0, ah1, ah2, ah3, al0, al1, al2, al3;
            ldsm_x4(ah0, ah1, ah2, ah3, smem + QHI_OFF + aoff);
            ldsm_x4(al0, al1, al2, al3, smem + QLO_OFF + aoff);
            #pragma unroll
            for (int nb = 0; nb < 2; nb++) {
                uint32_t boff = swz(brow + nb * 16, 2 * k + ((lane >> 3) & 1), 512);
                uint32_t bh0, bh1, bh2, bh3, bl0, bl1, bl2, bl3;
                ldsm_x4(bh0, bh1, bh2, bh3, kh + boff);
                ldsm_x4(bl0, bl1, bl2, bl3, kl + boff);
                mma16816(c[2 * nb], ah0, ah1, ah2, ah3, bh0, bh1);
                mma16816(c[2 * nb + 1], ah0, ah1, ah2, ah3, bh2, bh3);
                mma16816(c[2 * nb], ah0, ah1, ah2, ah3, bl0, bl1);
                mma16816(c[2 * nb + 1], ah0, ah1, ah2, ah3, bl2, bl3);
                mma16816(c[2 * nb], al0, al1, al2, al3, bh0, bh1);
                mma16816(c[2 * nb + 1], al0, al1, al2, al3, bh2, bh3);
            }
        }

        // ---- warp-local online softmax over these 32 cols ----
        float mx0 = -INFINITY, mx1 = -INFINITY;
        #pragma unroll
        for (int j = 0; j < 4; j++) {
            #pragma unroll
            for (int e = 0; e < 2; e++) {
                int col = j * 8 + 2 * lam + e;
                bool valid = (c0 + col) < L2v;
                float bias = p2f[col];
                float s0 = c[j][e] + p1a + bias;
                float s1v = c[j][e + 2] + p1b + bias;
                s0 = valid ? s0 : NEG_BIG;
                s1v = valid ? s1v : NEG_BIG;
                c[j][e] = s0; c[j][e + 2] = s1v;
                mx0 = fmaxf(mx0, s0); mx1 = fmaxf(mx1, s1v);
            }
        }
        mx0 = fmaxf(mx0, __shfl_xor_sync(0xffffffffu, mx0, 1));
        mx0 = fmaxf(mx0, __shfl_xor_sync(0xffffffffu, mx0, 2));
        mx1 = fmaxf(mx1, __shfl_xor_sync(0xffffffffu, mx1, 1));
        mx1 = fmaxf(mx1, __shfl_xor_sync(0xffffffffu, mx1, 2));

        const float mnew0 = fmaxf(mrow0, mx0), mnew1 = fmaxf(mrow1, mx1);
        const float alpha0 = __expf(mrow0 - mnew0), alpha1 = __expf(mrow1 - mnew1);
        mrow0 = mnew0; mrow1 = mnew1;

        float sum0 = 0.f, sum1 = 0.f;
        #pragma unroll
        for (int j = 0; j < 4; j++) {
            c[j][0] = __expf(c[j][0] - mnew0);
            c[j][1] = __expf(c[j][1] - mnew0);
            c[j][2] = __expf(c[j][2] - mnew1);
            c[j][3] = __expf(c[j][3] - mnew1);
            sum0 += c[j][0] + c[j][1];
            sum1 += c[j][2] + c[j][3];
        }
        sum0 += __shfl_xor_sync(0xffffffffu, sum0, 1);
        sum0 += __shfl_xor_sync(0xffffffffu, sum0, 2);
        sum1 += __shfl_xor_sync(0xffffffffu, sum1, 1);
        sum1 += __shfl_xor_sync(0xffffffffu, sum1, 2);
        lrow0 = lrow0 * alpha0 + sum0;
        lrow1 = lrow1 * alpha1 + sum1;

        // ---- pack P c-frags into PV a-frags (in registers) ----
        uint32_t pah[8], pal[8];
        #pragma unroll
        for (int kk = 0; kk < 2; kk++) {
            const int J = 2 * kk;
            split2(c[J][0],     c[J][1],     pah[4 * kk + 0], pal[4 * kk + 0]);
            split2(c[J][2],     c[J][3],     pah[4 * kk + 1], pal[4 * kk + 1]);
            split2(c[J + 1][0], c[J + 1][1], pah[4 * kk + 2], pal[4 * kk + 2]);
            split2(c[J + 1][2], c[J + 1][3], pah[4 * kk + 3], pal[4 * kk + 3]);
        }

        // ---- rescale O ----
        #pragma unroll
        for (int j = 0; j < 32; j++) {
            O[j][0] *= alpha0; O[j][1] *= alpha0;
            O[j][2] *= alpha1; O[j][3] *= alpha1;
        }

        // ---- PV: O += P(:, chunk) * V(chunk, :) ----
        #pragma unroll
        for (int kk = 0; kk < 2; kk++) {
            const int vrow = kk * 16 + (lane & 15);
            const uint32_t a0 = pah[4 * kk], a1 = pah[4 * kk + 1],
                           a2 = pah[4 * kk + 2], a3 = pah[4 * kk + 3];
            const uint32_t b0 = pal[4 * kk], b1 = pal[4 * kk + 1],
                           b2 = pal[4 * kk + 2], b3 = pal[4 * kk + 3];
            #pragma unroll
            for (int dblk = 0; dblk < 16; dblk++) {
                uint32_t boff = swz(vrow, 2 * dblk + (lane >> 4), 512);
                uint32_t vh0, vh1, vh2, vh3, vl0, vl1, vl2, vl3;
                ldsm_x4t(vh0, vh1, vh2, vh3, kh + boff);
                ldsm_x4t(vl0, vl1, vl2, vl3, kl + boff);
                mma16816(O[2 * dblk],     a0, a1, a2, a3, vh0, vh1);
                mma16816(O[2 * dblk + 1], a0, a1, a2, a3, vh2, vh3);
                mma16816(O[2 * dblk],     a0, a1, a2, a3, vl0, vl1);
                mma16816(O[2 * dblk + 1], a0, a1, a2, a3, vl2, vl3);
                mma16816(O[2 * dblk],     b0, b1, b2, b3, vh0, vh1);
                mma16816(O[2 * dblk + 1], b0, b1, b2, b3, vh2, vh3);
            }
        }
    }

    // ---------------- epilogue ----------------
    const int gr0 = m0 + r0l, gr1 = gr0 + 8;
    const float inv0 = (gr0 < L1v) ? (1.f / lrow0) : 0.f;
    const float inv1 = (gr1 < L1v) ? (1.f / lrow1) : 0.f;
    float* orow0 = outTile + r0l * DD + 2 * lam;
    float* orow1 = orow0 + 8 * DD;
    #pragma unroll
    for (int j = 0; j < 32; j++) {
        float2 v0; v0.x = O[j][0] * inv0; v0.y = O[j][1] * inv0;
        float2 v1; v1.x = O[j][2] * inv1; v1.y = O[j][3] * inv1;
        *(float2*)(orow0 + j * 8) = v0;
        *(float2*)(orow1 + j * 8) = v1;
    }
}

extern "C" void kernel_launch(void* const* d_in, const int* in_sizes, int n_in,
                              void* d_out, int out_size)
{
    const float* s1 = (const float*)d_in[0];
    const float* s2 = (const float*)d_in[1];
    const float* w  = (const float*)d_in[2];
    const int*   l1 = (const int*)d_in[3];
    const int*   l2 = (const int*)d_in[4];
    float* out = (float*)d_out;

    const int B  = in_sizes[3];
    const int D  = in_sizes[2] / 3;
    const int t1 = in_sizes[0] / (B * D);
    const int t2 = in_sizes[1] / (B * D);
    const int total_rows = B * t2;

    prep_s2<<<(total_rows + 31) / 32, 256>>>(s2, w, total_rows);

    cudaFuncSetAttribute(bidaf_fa2, cudaFuncAttributeMaxDynamicSharedMemorySize,
                         SMEM_BYTES);
    dim3 grid(t1 / 128, B);
    bidaf_fa2<<<grid, NT, SMEM_BYTES>>>(s1, s2, w, l1, l2, out);
}